// round 8
// baseline (speedup 1.0000x reference)
#include <cuda_runtime.h>
#include <cstdint>

// SoftNormalShader: gather vertex normals + barycentric interp + softmax RGB blend.
// N=4,H=512,W=512,K=8 ; V=50000, F=100000.
// Inputs (JAX x64 disabled => int arrays are int32):
//   0: verts_normals (V,3) f32   1: bary (P,8,3) f32   2: dists (P,8) f32
//   3: zbuf (P,8) f32            4: faces (F,3) i32    5: pix_to_face (P,8) i32
// Output: (N,H,W,4) float32
//
// R8: 2 px/thread front-batched loads; pass 1 reduced to two scalars
// (alpha-product, zmax) so no pm/zi arrays are held live -> smaller register
// set -> 6 blocks/SM (75% occ). Selected samples (~1.06 of 8, GAMMA=1e-4
// underflow) recompute their sigmoid. Per-face normal table (L2-resident)
// kills the faces->vn double indirection; lazy bary with b2 reconstructed.

#define KSAMP 8
#define SIGMA_INV  1e4f
#define GAMMA_INV  1e4f
#define ZFAR_F     100.0f
#define INV_RANGE  (1.0f / 99.0f)
#define EPS_F      1e-10f

#define MAXF 131072

__device__ float4 g_fn[MAXF][3];   // per-face packed vertex normals

__global__ __launch_bounds__(256)
void prep_face_normals_kernel(const float* __restrict__ vn,
                              const int*   __restrict__ faces, int F)
{
    int idx = blockIdx.x * blockDim.x + threadIdx.x;   // (face, vert) pairs
    int f = idx / 3;
    int j = idx - f * 3;
    if (f >= F || f >= MAXF) return;
    int v = __ldg(faces + (long long)f * 3 + j);
    const float* n = vn + (long long)v * 3;
    float x = __ldg(n + 0);
    float y = __ldg(n + 1);
    float z = __ldg(n + 2);
    g_fn[f][j] = make_float4(x, y, z, 0.0f);
}

#define PIX_PER_THREAD 2

__global__ __launch_bounds__(256, 6)
void soft_normal_shader_kernel(
    const float* __restrict__ bary,    // (P,8,3)
    const float* __restrict__ dists,   // (P,8)
    const float* __restrict__ zbuf,    // (P,8)
    const int*   __restrict__ p2f,     // (P,8)
    float4*      __restrict__ out,     // (P,) rgba
    int npix)
{
    int tid = blockIdx.x * blockDim.x + threadIdx.x;
    int nthreads = gridDim.x * blockDim.x;

    float4 dv[PIX_PER_THREAD][2], zv[PIX_PER_THREAD][2];
    int4   pv[PIX_PER_THREAD][2];

    // ---- front-batched streaming loads for both pixels (12 x 16B in flight) ----
    #pragma unroll
    for (int j = 0; j < PIX_PER_THREAD; j++) {
        int pix = tid + j * nthreads;
        if (pix >= npix) pix = npix - 1;           // safe clamp (grid is exact anyway)
        const long long base = (long long)pix * KSAMP;
        const float4* dp = reinterpret_cast<const float4*>(dists + base);
        const float4* zp = reinterpret_cast<const float4*>(zbuf  + base);
        const int4*   pp = reinterpret_cast<const int4*>(p2f + base);
        dv[j][0] = __ldcs(dp + 0); dv[j][1] = __ldcs(dp + 1);
        zv[j][0] = __ldcs(zp + 0); zv[j][1] = __ldcs(zp + 1);
        pv[j][0] = __ldcs(pp + 0); pv[j][1] = __ldcs(pp + 1);
    }

    #pragma unroll
    for (int j = 0; j < PIX_PER_THREAD; j++) {
        int pix = tid + j * nthreads;
        if (pix >= npix) continue;
        const long long base = (long long)pix * KSAMP;

        const float* df = reinterpret_cast<const float*>(&dv[j][0]);
        const float* zf = reinterpret_cast<const float*>(&zv[j][0]);
        const int*   pf = reinterpret_cast<const int*>(&pv[j][0]);

        // ---- pass 1: only two scalars survive (alpha product, zmax) ----
        float zmax = 0.0f;                 // z_inv >= 0 (masked entries are 0)
        float one_minus_prod = 1.0f;
        #pragma unroll
        for (int k = 0; k < KSAMP; k++) {
            bool valid = pf[k] >= 0;
            float p = valid ? (1.0f / (1.0f + __expf(df[k] * SIGMA_INV))) : 0.0f;
            one_minus_prod *= (1.0f - p);
            float z = valid ? (ZFAR_F - zf[k]) * INV_RANGE : 0.0f;
            zmax = fmaxf(zmax, z);
        }

        // ---- pass 2a: candidate mask (exp flushes to 0 below ~-88) ----
        unsigned mask = 0;
        #pragma unroll
        for (int k = 0; k < KSAMP; k++) {
            float z = (ZFAR_F - zf[k]) * INV_RANGE;
            if (pf[k] >= 0 && (z - zmax) * GAMMA_INV > -88.0f)
                mask |= (1u << k);
        }

        // ---- pass 2b: compacted weight + gather loop (typically 1 iter) ----
        float wsum = 0.0f;
        float accr = 0.0f, accg = 0.0f, accb = 0.0f;
        while (mask) {
            int k = __ffs(mask) - 1;
            mask &= mask - 1;
            float z = (ZFAR_F - zf[k]) * INV_RANGE;
            float p = 1.0f / (1.0f + __expf(df[k] * SIGMA_INV));   // recompute (rare)
            float w = p * __expf((z - zmax) * GAMMA_INV);
            wsum += w;
            // lazy bary: b0,b1 loaded; b2 reconstructed (sum == 1)
            const float* bp = bary + (base + k) * 3;
            float b0 = __ldg(bp + 0);
            float b1 = __ldg(bp + 1);
            float b2 = 1.0f - b0 - b1;
            // single-hop gather: per-face packed normals (L2-resident)
            const float4* fn = g_fn[pf[k]];
            float4 n0 = __ldg(fn + 0);
            float4 n1 = __ldg(fn + 1);
            float4 n2 = __ldg(fn + 2);
            accr += w * (b0 * n0.x + b1 * n1.x + b2 * n2.x);
            accg += w * (b0 * n0.y + b1 * n1.y + b2 * n2.y);
            accb += w * (b0 * n0.z + b1 * n1.z + b2 * n2.z);
        }

        // ---- blend ----
        float delta = fmaxf(__expf((EPS_F - zmax) * GAMMA_INV), EPS_F);
        float inv_denom = 1.0f / (wsum + delta);
        float4 o;
        o.x = (accr + delta) * inv_denom;   // background = (1,1,1)
        o.y = (accg + delta) * inv_denom;
        o.z = (accb + delta) * inv_denom;
        o.w = 1.0f - one_minus_prod;        // 1 - alpha
        __stcs(out + pix, o);
    }
}

extern "C" void kernel_launch(void* const* d_in, const int* in_sizes, int n_in,
                              void* d_out, int out_size)
{
    const float* vn    = (const float*)d_in[0];
    const float* bary  = (const float*)d_in[1];
    const float* dists = (const float*)d_in[2];
    const float* zbuf  = (const float*)d_in[3];
    const int*   faces = (const int*)d_in[4];
    const int*   p2f   = (const int*)d_in[5];
    float4*      out   = (float4*)d_out;

    int F = in_sizes[4] / 3;
    int npix = in_sizes[2] / KSAMP;   // N*H*W

    prep_face_normals_kernel<<<(3 * F + 255) / 256, 256>>>(vn, faces, F);

    int threads = 256;
    int total_threads = (npix + PIX_PER_THREAD - 1) / PIX_PER_THREAD;
    int blocks = (total_threads + threads - 1) / threads;
    soft_normal_shader_kernel<<<blocks, threads>>>(bary, dists, zbuf, p2f, out, npix);
}

// round 9
// speedup vs baseline: 1.3092x; 1.3092x over previous
#include <cuda_runtime.h>
#include <cstdint>

// SoftNormalShader: gather vertex normals + barycentric interp + softmax RGB blend.
// N=4,H=512,W=512,K=8 ; V=50000, F=100000.
// Inputs (JAX x64 disabled => int arrays are int32):
//   0: verts_normals (V,3) f32   1: bary (P,8,3) f32   2: dists (P,8) f32
//   3: zbuf (P,8) f32            4: faces (F,3) i32    5: pix_to_face (P,8) i32
// Output: (N,H,W,4) float32
//
// R9: R7 structure (2 px/thread, front-batched __ldcs loads, lb(256,5)) but
// the weight+gather pass is FULLY UNROLLED with static indexing only — R8
// proved dynamic indexing (while/__ffs) demotes the load buffers to local
// memory (+150 MB DRAM). Gather body is predicated per-k; only ~1.06 of 8
// samples pass (GAMMA=1e-4 underflow). Per-face normal table (L2-resident)
// removes the faces->vn double indirection; lazy bary with b2 reconstructed.

#define KSAMP 8
#define SIGMA_INV  1e4f
#define GAMMA_INV  1e4f
#define ZFAR_F     100.0f
#define INV_RANGE  (1.0f / 99.0f)
#define EPS_F      1e-10f

#define MAXF 131072

__device__ float4 g_fn[MAXF][3];   // per-face packed vertex normals

__global__ __launch_bounds__(256)
void prep_face_normals_kernel(const float* __restrict__ vn,
                              const int*   __restrict__ faces, int F)
{
    int idx = blockIdx.x * blockDim.x + threadIdx.x;   // (face, vert) pairs
    int f = idx / 3;
    int j = idx - f * 3;
    if (f >= F || f >= MAXF) return;
    int v = __ldg(faces + (long long)f * 3 + j);
    const float* n = vn + (long long)v * 3;
    float x = __ldg(n + 0);
    float y = __ldg(n + 1);
    float z = __ldg(n + 2);
    g_fn[f][j] = make_float4(x, y, z, 0.0f);
}

#define PIX_PER_THREAD 2

__global__ __launch_bounds__(256, 5)
void soft_normal_shader_kernel(
    const float* __restrict__ bary,    // (P,8,3)
    const float* __restrict__ dists,   // (P,8)
    const float* __restrict__ zbuf,    // (P,8)
    const int*   __restrict__ p2f,     // (P,8)
    float4*      __restrict__ out,     // (P,) rgba
    int npix)
{
    int tid = blockIdx.x * blockDim.x + threadIdx.x;
    int nthreads = gridDim.x * blockDim.x;

    float4 dv[PIX_PER_THREAD][2], zv[PIX_PER_THREAD][2];
    int4   pv[PIX_PER_THREAD][2];

    // ---- front-batched streaming loads for both pixels (12 x 16B in flight) ----
    #pragma unroll
    for (int j = 0; j < PIX_PER_THREAD; j++) {
        int pix = tid + j * nthreads;
        if (pix >= npix) pix = npix - 1;           // safe clamp (grid is exact anyway)
        const long long base = (long long)pix * KSAMP;
        const float4* dp = reinterpret_cast<const float4*>(dists + base);
        const float4* zp = reinterpret_cast<const float4*>(zbuf  + base);
        const int4*   pp = reinterpret_cast<const int4*>(p2f + base);
        dv[j][0] = __ldcs(dp + 0); dv[j][1] = __ldcs(dp + 1);
        zv[j][0] = __ldcs(zp + 0); zv[j][1] = __ldcs(zp + 1);
        pv[j][0] = __ldcs(pp + 0); pv[j][1] = __ldcs(pp + 1);
    }

    #pragma unroll
    for (int j = 0; j < PIX_PER_THREAD; j++) {
        int pix = tid + j * nthreads;
        if (pix >= npix) continue;
        const long long base = (long long)pix * KSAMP;

        // static unpack into scalars (all register-resident)
        float df[KSAMP] = { dv[j][0].x, dv[j][0].y, dv[j][0].z, dv[j][0].w,
                            dv[j][1].x, dv[j][1].y, dv[j][1].z, dv[j][1].w };
        float zf[KSAMP] = { zv[j][0].x, zv[j][0].y, zv[j][0].z, zv[j][0].w,
                            zv[j][1].x, zv[j][1].y, zv[j][1].z, zv[j][1].w };
        int   pf[KSAMP] = { pv[j][0].x, pv[j][0].y, pv[j][0].z, pv[j][0].w,
                            pv[j][1].x, pv[j][1].y, pv[j][1].z, pv[j][1].w };

        // ---- pass 1: sigmoid probs, z_inv, zmax, alpha product ----
        float pm[KSAMP], zi[KSAMP];
        float zmax = 0.0f;                 // z_inv >= 0 (masked entries are 0)
        float one_minus_prod = 1.0f;
        #pragma unroll
        for (int k = 0; k < KSAMP; k++) {
            bool valid = pf[k] >= 0;
            float p = valid ? (1.0f / (1.0f + __expf(df[k] * SIGMA_INV))) : 0.0f;
            pm[k] = p;
            one_minus_prod *= (1.0f - p);
            zi[k] = valid ? (ZFAR_F - zf[k]) * INV_RANGE : 0.0f;
            zmax = fmaxf(zmax, zi[k]);
        }

        // ---- pass 2: unrolled predicated weight + gather (static indexing) ----
        float wsum = 0.0f;
        float accr = 0.0f, accg = 0.0f, accb = 0.0f;
        #pragma unroll
        for (int k = 0; k < KSAMP; k++) {
            float e = (zi[k] - zmax) * GAMMA_INV;
            // exp flushes to 0 below ~-88; skip gather entirely (bit-exact)
            if (pf[k] >= 0 && e > -88.0f) {
                float w = pm[k] * __expf(e);
                wsum += w;
                // lazy bary: b0,b1 loaded; b2 reconstructed (sum == 1)
                const float* bp = bary + (base + k) * 3;
                float b0 = __ldg(bp + 0);
                float b1 = __ldg(bp + 1);
                float b2 = 1.0f - b0 - b1;
                // single-hop gather: per-face packed normals (L2-resident)
                const float4* fn = g_fn[pf[k]];
                float4 n0 = __ldg(fn + 0);
                float4 n1 = __ldg(fn + 1);
                float4 n2 = __ldg(fn + 2);
                accr += w * (b0 * n0.x + b1 * n1.x + b2 * n2.x);
                accg += w * (b0 * n0.y + b1 * n1.y + b2 * n2.y);
                accb += w * (b0 * n0.z + b1 * n1.z + b2 * n2.z);
            }
        }

        // ---- blend ----
        float delta = fmaxf(__expf((EPS_F - zmax) * GAMMA_INV), EPS_F);
        float inv_denom = 1.0f / (wsum + delta);
        float4 o;
        o.x = (accr + delta) * inv_denom;   // background = (1,1,1)
        o.y = (accg + delta) * inv_denom;
        o.z = (accb + delta) * inv_denom;
        o.w = 1.0f - one_minus_prod;        // 1 - alpha
        __stcs(out + pix, o);
    }
}

extern "C" void kernel_launch(void* const* d_in, const int* in_sizes, int n_in,
                              void* d_out, int out_size)
{
    const float* vn    = (const float*)d_in[0];
    const float* bary  = (const float*)d_in[1];
    const float* dists = (const float*)d_in[2];
    const float* zbuf  = (const float*)d_in[3];
    const int*   faces = (const int*)d_in[4];
    const int*   p2f   = (const int*)d_in[5];
    float4*      out   = (float4*)d_out;

    int F = in_sizes[4] / 3;
    int npix = in_sizes[2] / KSAMP;   // N*H*W

    prep_face_normals_kernel<<<(3 * F + 255) / 256, 256>>>(vn, faces, F);

    int threads = 256;
    int total_threads = (npix + PIX_PER_THREAD - 1) / PIX_PER_THREAD;
    int blocks = (total_threads + threads - 1) / threads;
    soft_normal_shader_kernel<<<blocks, threads>>>(bary, dists, zbuf, p2f, out, npix);
}

// round 10
// speedup vs baseline: 1.6235x; 1.2401x over previous
#include <cuda_runtime.h>
#include <cstdint>

// SoftNormalShader: gather vertex normals + barycentric interp + softmax RGB blend.
// N=4,H=512,W=512,K=8 ; V=50000, F=100000.
// Inputs (JAX x64 disabled => int arrays are int32):
//   0: verts_normals (V,3) f32   1: bary (P,8,3) f32   2: dists (P,8) f32
//   3: zbuf (P,8) f32            4: faces (F,3) i32    5: pix_to_face (P,8) i32
// Output: (N,H,W,4) float32
//
// R10: compacted while(mask) gather loop (R7's warp-efficient control flow:
// different lanes' passing k's execute in the same iteration) but all dynamic
// per-k accesses go through 7-select binary trees over named registers — R8/R9
// proved dynamic array indexing demotes buffers to local memory (+20..150 MB
// DRAM). ~1.06 of 8 samples pass (GAMMA=1e-4 underflow). Per-face normal
// table (L2-resident) removes the faces->vn double indirection; lazy bary.

#define KSAMP 8
#define SIGMA_INV  1e4f
#define GAMMA_INV  1e4f
#define ZFAR_F     100.0f
#define INV_RANGE  (1.0f / 99.0f)
#define EPS_F      1e-10f

#define MAXF 131072

__device__ float4 g_fn[MAXF][3];   // per-face packed vertex normals

__global__ __launch_bounds__(256)
void prep_face_normals_kernel(const float* __restrict__ vn,
                              const int*   __restrict__ faces, int F)
{
    int idx = blockIdx.x * blockDim.x + threadIdx.x;   // (face, vert) pairs
    int f = idx / 3;
    int j = idx - f * 3;
    if (f >= F || f >= MAXF) return;
    int v = __ldg(faces + (long long)f * 3 + j);
    const float* n = vn + (long long)v * 3;
    float x = __ldg(n + 0);
    float y = __ldg(n + 1);
    float z = __ldg(n + 2);
    g_fn[f][j] = make_float4(x, y, z, 0.0f);
}

// 7-select binary trees: dynamic k -> register value, no local memory.
__device__ __forceinline__ float sel8f(const float* v, int k) {
    float x01 = (k & 1) ? v[1] : v[0];
    float x23 = (k & 1) ? v[3] : v[2];
    float x45 = (k & 1) ? v[5] : v[4];
    float x67 = (k & 1) ? v[7] : v[6];
    float y0  = (k & 2) ? x23 : x01;
    float y1  = (k & 2) ? x67 : x45;
    return (k & 4) ? y1 : y0;
}
__device__ __forceinline__ int sel8i(const int* v, int k) {
    int x01 = (k & 1) ? v[1] : v[0];
    int x23 = (k & 1) ? v[3] : v[2];
    int x45 = (k & 1) ? v[5] : v[4];
    int x67 = (k & 1) ? v[7] : v[6];
    int y0  = (k & 2) ? x23 : x01;
    int y1  = (k & 2) ? x67 : x45;
    return (k & 4) ? y1 : y0;
}

#define PIX_PER_THREAD 2

__global__ __launch_bounds__(256, 5)
void soft_normal_shader_kernel(
    const float* __restrict__ bary,    // (P,8,3)
    const float* __restrict__ dists,   // (P,8)
    const float* __restrict__ zbuf,    // (P,8)
    const int*   __restrict__ p2f,     // (P,8)
    float4*      __restrict__ out,     // (P,) rgba
    int npix)
{
    int tid = blockIdx.x * blockDim.x + threadIdx.x;
    int nthreads = gridDim.x * blockDim.x;

    float4 dv[PIX_PER_THREAD][2], zv[PIX_PER_THREAD][2];
    int4   pv[PIX_PER_THREAD][2];

    // ---- front-batched streaming loads for both pixels (12 x 16B in flight) ----
    #pragma unroll
    for (int j = 0; j < PIX_PER_THREAD; j++) {
        int pix = tid + j * nthreads;
        if (pix >= npix) pix = npix - 1;           // safe clamp (grid is exact anyway)
        const long long base = (long long)pix * KSAMP;
        const float4* dp = reinterpret_cast<const float4*>(dists + base);
        const float4* zp = reinterpret_cast<const float4*>(zbuf  + base);
        const int4*   pp = reinterpret_cast<const int4*>(p2f + base);
        dv[j][0] = __ldcs(dp + 0); dv[j][1] = __ldcs(dp + 1);
        zv[j][0] = __ldcs(zp + 0); zv[j][1] = __ldcs(zp + 1);
        pv[j][0] = __ldcs(pp + 0); pv[j][1] = __ldcs(pp + 1);
    }

    #pragma unroll
    for (int j = 0; j < PIX_PER_THREAD; j++) {
        int pix = tid + j * nthreads;
        if (pix >= npix) continue;
        const long long base = (long long)pix * KSAMP;

        // statically-indexed scalar views (register-resident; unrolled only)
        float df[KSAMP] = { dv[j][0].x, dv[j][0].y, dv[j][0].z, dv[j][0].w,
                            dv[j][1].x, dv[j][1].y, dv[j][1].z, dv[j][1].w };
        float zf[KSAMP] = { zv[j][0].x, zv[j][0].y, zv[j][0].z, zv[j][0].w,
                            zv[j][1].x, zv[j][1].y, zv[j][1].z, zv[j][1].w };
        int   pf[KSAMP] = { pv[j][0].x, pv[j][0].y, pv[j][0].z, pv[j][0].w,
                            pv[j][1].x, pv[j][1].y, pv[j][1].z, pv[j][1].w };

        // ---- pass 1: sigmoid probs, exp-args, zmax, alpha product ----
        float pm[KSAMP], ze[KSAMP];
        float zmax = 0.0f;                 // z_inv >= 0 (masked entries are 0)
        float one_minus_prod = 1.0f;
        #pragma unroll
        for (int k = 0; k < KSAMP; k++) {
            bool valid = pf[k] >= 0;
            float p = valid ? (1.0f / (1.0f + __expf(df[k] * SIGMA_INV))) : 0.0f;
            pm[k] = p;
            one_minus_prod *= (1.0f - p);
            ze[k] = valid ? (ZFAR_F - zf[k]) * INV_RANGE : 0.0f;
            zmax = fmaxf(zmax, ze[k]);
        }

        // ---- candidate mask: exp((z-zmax)*1e4) flushes to 0 below ~-88 ----
        unsigned mask = 0;
        #pragma unroll
        for (int k = 0; k < KSAMP; k++) {
            float e = (ze[k] - zmax) * GAMMA_INV;
            if (pf[k] >= 0 && e > -88.0f)
                mask |= (1u << k);
        }

        // ---- compacted weight + gather loop (~1.06 iterations, lanes share) ----
        float wsum = 0.0f;
        float accr = 0.0f, accg = 0.0f, accb = 0.0f;
        while (mask) {
            int k = __ffs(mask) - 1;
            mask &= mask - 1;
            // register select trees — no local memory
            float z = sel8f(ze, k);
            float p = sel8f(pm, k);
            int   f = sel8i(pf, k);
            float w = p * __expf((z - zmax) * GAMMA_INV);
            wsum += w;
            // lazy bary: b0,b1 loaded; b2 reconstructed (sum == 1)
            const float* bp = bary + (base + k) * 3;
            float b0 = __ldg(bp + 0);
            float b1 = __ldg(bp + 1);
            float b2 = 1.0f - b0 - b1;
            // single-hop gather: per-face packed normals (L2-resident)
            const float4* fn = g_fn[f];
            float4 n0 = __ldg(fn + 0);
            float4 n1 = __ldg(fn + 1);
            float4 n2 = __ldg(fn + 2);
            accr += w * (b0 * n0.x + b1 * n1.x + b2 * n2.x);
            accg += w * (b0 * n0.y + b1 * n1.y + b2 * n2.y);
            accb += w * (b0 * n0.z + b1 * n1.z + b2 * n2.z);
        }

        // ---- blend ----
        float delta = fmaxf(__expf((EPS_F - zmax) * GAMMA_INV), EPS_F);
        float inv_denom = 1.0f / (wsum + delta);
        float4 o;
        o.x = (accr + delta) * inv_denom;   // background = (1,1,1)
        o.y = (accg + delta) * inv_denom;
        o.z = (accb + delta) * inv_denom;
        o.w = 1.0f - one_minus_prod;        // 1 - alpha
        __stcs(out + pix, o);
    }
}

extern "C" void kernel_launch(void* const* d_in, const int* in_sizes, int n_in,
                              void* d_out, int out_size)
{
    const float* vn    = (const float*)d_in[0];
    const float* bary  = (const float*)d_in[1];
    const float* dists = (const float*)d_in[2];
    const float* zbuf  = (const float*)d_in[3];
    const int*   faces = (const int*)d_in[4];
    const int*   p2f   = (const int*)d_in[5];
    float4*      out   = (float4*)d_out;

    int F = in_sizes[4] / 3;
    int npix = in_sizes[2] / KSAMP;   // N*H*W

    prep_face_normals_kernel<<<(3 * F + 255) / 256, 256>>>(vn, faces, F);

    int threads = 256;
    int total_threads = (npix + PIX_PER_THREAD - 1) / PIX_PER_THREAD;
    int blocks = (total_threads + threads - 1) / threads;
    soft_normal_shader_kernel<<<blocks, threads>>>(bary, dists, zbuf, p2f, out, npix);
}